// round 1
// baseline (speedup 1.0000x reference)
#include <cuda_runtime.h>
#include <math.h>

#define NB 64
#define NL 64
#define ND 512
#define TEMP1 4.0f
#define TEMP2 5.0f
#define TEMP3 10.0f
#define EPSV 1e-8f

// Scratch (allocation-free rule: __device__ globals)
__device__ float Gg[NB * NL * NL];   // Gram matrices per j: 1 MB
__device__ float w1g[NB * NL];       // ||sent[i,q]||
__device__ float simg[NB * NB];      // sim[j][i]

// ---------------------------------------------------------------------------
// w1: row norms of sent (4096 rows of 512). One warp per row.
__global__ void w1_kernel(const float* __restrict__ sent) {
    int row = blockIdx.x * 8 + (threadIdx.x >> 5);
    int lane = threadIdx.x & 31;
    const float* p = sent + (size_t)row * ND;
    float s = 0.f;
    #pragma unroll
    for (int d = lane; d < ND; d += 32) { float v = p[d]; s += v * v; }
    #pragma unroll
    for (int o = 16; o; o >>= 1) s += __shfl_xor_sync(0xffffffffu, s, o);
    if (lane == 0) w1g[row] = sqrtf(s);
}

// ---------------------------------------------------------------------------
// Gram: G_j = ecg_j @ ecg_j^T  (64x64x512), one CTA per j.
__global__ void __launch_bounds__(256) gram_kernel(const float* __restrict__ ecg) {
    __shared__ float tile[64][68];
    int j = blockIdx.x;
    int tid = threadIdx.x;
    int tx = tid & 15, ty = tid >> 4;
    const float* E = ecg + (size_t)j * NL * ND;

    float acc[4][4] = {};
    for (int kc = 0; kc < ND; kc += 64) {
        __syncthreads();
        for (int n = tid; n < 64 * 64; n += 256) {
            int r = n >> 6, d = n & 63;
            tile[d][r] = E[r * ND + kc + d];   // transposed store
        }
        __syncthreads();
        #pragma unroll 8
        for (int d = 0; d < 64; d++) {
            float4 a = *(const float4*)&tile[d][ty * 4];
            float4 b = *(const float4*)&tile[d][tx * 4];
            acc[0][0] += a.x * b.x; acc[0][1] += a.x * b.y; acc[0][2] += a.x * b.z; acc[0][3] += a.x * b.w;
            acc[1][0] += a.y * b.x; acc[1][1] += a.y * b.y; acc[1][2] += a.y * b.z; acc[1][3] += a.y * b.w;
            acc[2][0] += a.z * b.x; acc[2][1] += a.z * b.y; acc[2][2] += a.z * b.z; acc[2][3] += a.z * b.w;
            acc[3][0] += a.w * b.x; acc[3][1] += a.w * b.y; acc[3][2] += a.w * b.z; acc[3][3] += a.w * b.w;
        }
    }
    float* Gj = Gg + (size_t)j * NL * NL;
    #pragma unroll
    for (int ss = 0; ss < 4; ss++)
        #pragma unroll
        for (int qq = 0; qq < 4; qq++)
            Gj[(ty * 4 + ss) * NL + tx * 4 + qq] = acc[ss][qq];
}

// ---------------------------------------------------------------------------
// Main fused kernel: one CTA per (i, j) pair.
//   S = ecg_j @ sent_i^T (64x64), softmax over q, transposed softmax over s,
//   w12, w2 via Gram, sim entry, att_maps for diagonal pairs.
__global__ void __launch_bounds__(256) pair_kernel(const float* __restrict__ ecg,
                                                   const float* __restrict__ sent,
                                                   float* __restrict__ out) {
    __shared__ float bufE[64][68];  // Etile -> S -> G
    __shared__ float bufQ[64][68];  // Qtile -> attn1 -> A (transposed, [q][s])
    __shared__ float w12s[64];
    __shared__ float w2sqs[64];
    __shared__ float ssum;

    int i = blockIdx.x;  // sent batch index
    int j = blockIdx.y;  // ecg batch index
    int tid = threadIdx.x;
    int tx = tid & 15, ty = tid >> 4;

    const float* E = ecg + (size_t)j * NL * ND;
    const float* Q = sent + (size_t)i * NL * ND;

    // ---- GEMM: S[s][q] = sum_d E[s][d] * Q[q][d]
    float acc[4][4] = {};
    for (int kc = 0; kc < ND; kc += 64) {
        __syncthreads();
        for (int n = tid; n < 64 * 64; n += 256) {
            int r = n >> 6, d = n & 63;
            bufE[d][r] = E[r * ND + kc + d];
            bufQ[d][r] = Q[r * ND + kc + d];
        }
        __syncthreads();
        #pragma unroll 8
        for (int d = 0; d < 64; d++) {
            float4 a = *(const float4*)&bufE[d][ty * 4];
            float4 b = *(const float4*)&bufQ[d][tx * 4];
            acc[0][0] += a.x * b.x; acc[0][1] += a.x * b.y; acc[0][2] += a.x * b.z; acc[0][3] += a.x * b.w;
            acc[1][0] += a.y * b.x; acc[1][1] += a.y * b.y; acc[1][2] += a.y * b.z; acc[1][3] += a.y * b.w;
            acc[2][0] += a.z * b.x; acc[2][1] += a.z * b.y; acc[2][2] += a.z * b.z; acc[2][3] += a.z * b.w;
            acc[3][0] += a.w * b.x; acc[3][1] += a.w * b.y; acc[3][2] += a.w * b.z; acc[3][3] += a.w * b.w;
        }
    }
    __syncthreads();
    // write S to bufE: S[s][q]
    #pragma unroll
    for (int ss = 0; ss < 4; ss++)
        #pragma unroll
        for (int qq = 0; qq < 4; qq++)
            bufE[ty * 4 + ss][tx * 4 + qq] = acc[ss][qq];
    if (tid < 64) w2sqs[tid] = 0.f;
    if (tid == 0) ssum = 0.f;
    __syncthreads();

    // ---- softmax 1: over q, per row s.  attn1[s][q] -> bufQ[s][q]
    {
        int g = tid >> 2, l = tid & 3;  // row g, 4 threads per row
        float v[16];
        float mx = -1e30f;
        #pragma unroll
        for (int m = 0; m < 16; m++) { v[m] = bufE[g][l * 16 + m]; mx = fmaxf(mx, v[m]); }
        mx = fmaxf(mx, __shfl_xor_sync(0xffffffffu, mx, 1));
        mx = fmaxf(mx, __shfl_xor_sync(0xffffffffu, mx, 2));
        float sm = 0.f;
        #pragma unroll
        for (int m = 0; m < 16; m++) { v[m] = __expf(v[m] - mx); sm += v[m]; }
        sm += __shfl_xor_sync(0xffffffffu, sm, 1);
        sm += __shfl_xor_sync(0xffffffffu, sm, 2);
        float inv = 1.f / sm;
        #pragma unroll
        for (int m = 0; m < 16; m++) bufQ[g][l * 16 + m] = v[m] * inv;
    }
    __syncthreads();

    // ---- softmax 2 (over s, per q) with in-place transpose: A[q][s] -> bufQ[q][s]
    float e[16];
    float invs;
    {
        int q = tid >> 2, l = tid & 3;
        float mx = -1e30f;
        #pragma unroll
        for (int m = 0; m < 16; m++) { e[m] = TEMP1 * bufQ[l * 16 + m][q]; mx = fmaxf(mx, e[m]); }
        mx = fmaxf(mx, __shfl_xor_sync(0xffffffffu, mx, 1));
        mx = fmaxf(mx, __shfl_xor_sync(0xffffffffu, mx, 2));
        float sm = 0.f;
        #pragma unroll
        for (int m = 0; m < 16; m++) { e[m] = __expf(e[m] - mx); sm += e[m]; }
        sm += __shfl_xor_sync(0xffffffffu, sm, 1);
        sm += __shfl_xor_sync(0xffffffffu, sm, 2);
        invs = 1.f / sm;
    }
    __syncthreads();  // all reads of attn1 complete before overwrite
    {
        int q = tid >> 2, l = tid & 3;
        float w12p = 0.f;
        #pragma unroll
        for (int m = 0; m < 16; m++) {
            int s = l * 16 + m;
            float a = e[m] * invs;
            bufQ[q][s] = a;
            w12p += a * bufE[s][q];  // S[s][q]
        }
        w12p += __shfl_xor_sync(0xffffffffu, w12p, 1);
        w12p += __shfl_xor_sync(0xffffffffu, w12p, 2);
        if (l == 0) w12s[q] = w12p;
    }
    __syncthreads();

    // ---- load G_j into bufE (S no longer needed)
    const float* Gj = Gg + (size_t)j * NL * NL;
    for (int n = tid; n < 64 * 64; n += 256) bufE[n >> 6][n & 63] = Gj[n];
    __syncthreads();

    // ---- M = A @ G_j ; w2sq[q] = sum_t M[q][t] * A[q][t]
    {
        float acc2[4][4] = {};
        #pragma unroll 8
        for (int u = 0; u < 64; u++) {
            float a0 = bufQ[ty * 4 + 0][u];
            float a1 = bufQ[ty * 4 + 1][u];
            float a2 = bufQ[ty * 4 + 2][u];
            float a3 = bufQ[ty * 4 + 3][u];
            float4 b = *(const float4*)&bufE[u][tx * 4];
            acc2[0][0] += a0 * b.x; acc2[0][1] += a0 * b.y; acc2[0][2] += a0 * b.z; acc2[0][3] += a0 * b.w;
            acc2[1][0] += a1 * b.x; acc2[1][1] += a1 * b.y; acc2[1][2] += a1 * b.z; acc2[1][3] += a1 * b.w;
            acc2[2][0] += a2 * b.x; acc2[2][1] += a2 * b.y; acc2[2][2] += a2 * b.z; acc2[2][3] += a2 * b.w;
            acc2[3][0] += a3 * b.x; acc2[3][1] += a3 * b.y; acc2[3][2] += a3 * b.z; acc2[3][3] += a3 * b.w;
        }
        #pragma unroll
        for (int ss = 0; ss < 4; ss++) {
            int q = ty * 4 + ss;
            float p = 0.f;
            #pragma unroll
            for (int qq = 0; qq < 4; qq++) p += acc2[ss][qq] * bufQ[q][tx * 4 + qq];
            atomicAdd(&w2sqs[q], p);
        }
    }
    __syncthreads();

    // ---- cos, partial logsumexp-over-q
    if (tid < 64) {
        int q = tid;
        float w2 = sqrtf(w2sqs[q]);
        float cosv = w12s[q] / fmaxf(w1g[i * NL + q] * w2, EPSV);
        atomicAdd(&ssum, __expf(TEMP2 * cosv));
    }
    __syncthreads();
    if (tid == 0) simg[j * NB + i] = TEMP3 * logf(ssum);

    // ---- att_maps for diagonal pairs: attn[i,i][q][s]
    if (i == j) {
        float* om = out + 1 + (size_t)i * NL * NL;
        for (int n = tid; n < 64 * 64; n += 256) om[n] = bufQ[n >> 6][n & 63];
    }
}

// ---------------------------------------------------------------------------
// Loss: symmetric log-softmax on 64x64 sim, diagonal mean. 1 CTA, 64 threads.
__global__ void loss_kernel(float* __restrict__ out) {
    __shared__ float acc0;
    int b = threadIdx.x;
    if (b == 0) acc0 = 0.f;
    __syncthreads();
    float mr = -1e30f, mc = -1e30f;
    for (int k = 0; k < NB; k++) {
        mr = fmaxf(mr, simg[b * NB + k]);
        mc = fmaxf(mc, simg[k * NB + b]);
    }
    float sr = 0.f, sc = 0.f;
    for (int k = 0; k < NB; k++) {
        sr += expf(simg[b * NB + k] - mr);
        sc += expf(simg[k * NB + b] - mc);
    }
    float diag = simg[b * NB + b];
    float lp0 = diag - mr - logf(sr);
    float lp1 = diag - mc - logf(sc);
    atomicAdd(&acc0, lp0 + lp1);
    __syncthreads();
    if (b == 0) out[0] = -acc0 / (2.0f * (float)NB);
}

// ---------------------------------------------------------------------------
extern "C" void kernel_launch(void* const* d_in, const int* in_sizes, int n_in,
                              void* d_out, int out_size) {
    const float* ecg = (const float*)d_in[0];   // (64, 64, 512) fp32
    const float* sent = (const float*)d_in[1];  // (64, 64, 512) fp32
    float* out = (float*)d_out;                 // [loss, att_maps(64*64*64)]

    w1_kernel<<<NB * NL / 8, 256>>>(sent);
    gram_kernel<<<NB, 256>>>(ecg);
    dim3 grid(NB, NB);
    pair_kernel<<<grid, 256>>>(ecg, sent, out);
    loss_kernel<<<1, NB>>>(out);
}